// round 1
// baseline (speedup 1.0000x reference)
#include <cuda_runtime.h>

#define TT 12
#define SS 16
#define NTHREADS 256
#define YSTRIDE 17   // 16 species + sentinel 1.0f; 17 coprime with 32 -> conflict-free

struct MechParams {
    int   sub[TT];     // substrate species index (always valid)
    int   prod[TT];    // product species index, 16 (sentinel) if none
    int   fr[TT];      // forward enzyme index, 16 if invalid
    int   to[TT];      // reverse enzyme index, 16 if invalid
    float rev[TT];     // 1.0 if reversible else 0.0
    float eff[TT][SS]; // net-effect matrix
};

__device__ MechParams g_mp;

// Robustly decode a boolean array whose on-device dtype may be int32,
// uint8/bool, or float32. Only the first min(n,12) bytes are read before
// committing to a wider interpretation, so no OOB under any hypothesis.
__device__ void decode_bools(const unsigned char* p, int n, int* out) {
    // float32 1.0f has byte pattern [00 00 80 3F]
    bool is_f32 = false;
    for (int k = 0; k < 3; k++)
        if (p[4 * k + 2] == 0x80 && p[4 * k + 3] == 0x3F) is_f32 = true;
    if (is_f32) {
        const float* fp = (const float*)p;
        for (int i = 0; i < n; i++) out[i] = (fp[i] != 0.0f) ? 1 : 0;
        return;
    }
    // uint8/bool: nonzero bytes appear at non-multiple-of-4 positions
    bool off_nonzero = false;
    for (int j = 0; j < 12 && j < n; j++)
        if ((j & 3) && p[j]) off_nonzero = true;
    if (off_nonzero) {
        for (int i = 0; i < n; i++) out[i] = (p[i] != 0) ? 1 : 0;
        return;
    }
    // int32 (values 0/1, little-endian: [v 0 0 0])
    const int* ip = (const int*)p;
    for (int i = 0; i < n; i++) out[i] = (ip[i] != 0) ? 1 : 0;
}

__global__ void prep_kernel(const float* __restrict__ stoich,
                            const float* __restrict__ effects,
                            const int* __restrict__ from_idx,
                            const unsigned char* __restrict__ from_valid,
                            const int* __restrict__ to_idx,
                            const unsigned char* __restrict__ to_valid,
                            const unsigned char* __restrict__ reversible)
{
    if (threadIdx.x != 0 || blockIdx.x != 0) return;
    int fvv[TT], tvv[TT], rvv[TT];
    decode_bools(from_valid, TT, fvv);
    decode_bools(to_valid, TT, tvv);
    decode_bools(reversible, TT, rvv);
    for (int t = 0; t < TT; t++) {
        int sub = -1, prod = -1;
        for (int s = 0; s < SS; s++) {
            float v = stoich[t * SS + s];
            if (v < -0.5f) sub = s;
            if (v >  0.5f) prod = s;
        }
        g_mp.sub[t]  = (sub  >= 0) ? sub  : 16;
        g_mp.prod[t] = (prod >= 0) ? prod : 16;
        g_mp.fr[t]   = fvv[t] ? from_idx[t] : 16;
        g_mp.to[t]   = tvv[t] ? to_idx[t]   : 16;
        g_mp.rev[t]  = rvv[t] ? 1.0f : 0.0f;
        for (int s = 0; s < SS; s++)
            g_mp.eff[t][s] = effects[t * SS + s];
    }
}

__global__ void __launch_bounds__(NTHREADS)
mech_kernel(const float4* __restrict__ y4,
            const float4* __restrict__ f4,
            const float4* __restrict__ r4,
            float4* __restrict__ out4,
            int B)
{
    __shared__ float ys[NTHREADS * YSTRIDE];
    __shared__ MechParams smp;

    const int tid = threadIdx.x;

    // Cooperative copy of the tiny parameter block into smem
    {
        constexpr unsigned nwords = sizeof(MechParams) / 4;
        const unsigned* src = (const unsigned*)&g_mp;
        unsigned* dst = (unsigned*)&smp;
        for (unsigned i = tid; i < nwords; i += NTHREADS) dst[i] = src[i];
    }

    const long b = (long)blockIdx.x * NTHREADS + tid;
    const bool active = (b < B);
    const int base = tid * YSTRIDE;

    float fv[TT], rv[TT];
    if (active) {
        // y row: 16 floats = 4x float4, staged to smem for dynamic gathers
        #pragma unroll
        for (int k = 0; k < 4; k++) {
            float4 v = y4[b * 4 + k];
            ys[base + 4 * k + 0] = v.x;
            ys[base + 4 * k + 1] = v.y;
            ys[base + 4 * k + 2] = v.z;
            ys[base + 4 * k + 3] = v.w;
        }
        ys[base + 16] = 1.0f;  // sentinel for invalid enzyme / missing product

        // forward / reverse rate rows: 12 floats = 3x float4 each
        #pragma unroll
        for (int k = 0; k < 3; k++) {
            float4 a = f4[b * 3 + k];
            fv[4 * k + 0] = a.x; fv[4 * k + 1] = a.y;
            fv[4 * k + 2] = a.z; fv[4 * k + 3] = a.w;
            float4 c = r4[b * 3 + k];
            rv[4 * k + 0] = c.x; rv[4 * k + 1] = c.y;
            rv[4 * k + 2] = c.z; rv[4 * k + 3] = c.w;
        }
    }
    __syncthreads();

    if (!active) return;

    float acc[SS];
    #pragma unroll
    for (int s = 0; s < SS; s++) acc[s] = 0.0f;

    #pragma unroll
    for (int t = 0; t < TT; t++) {
        // Indices are uniform across the warp; smem stride 17 keeps banks distinct.
        float sc = ys[base + smp.sub[t]];
        float ef = ys[base + smp.fr[t]];
        float pc = ys[base + smp.prod[t]];
        float er = ys[base + smp.to[t]];
        float v  = fv[t] * ef * sc - smp.rev[t] * rv[t] * er * pc;
        #pragma unroll
        for (int s = 0; s < SS; s++)
            acc[s] = fmaf(v, smp.eff[t][s], acc[s]);
    }

    #pragma unroll
    for (int k = 0; k < 4; k++) {
        float4 o;
        o.x = acc[4 * k + 0];
        o.y = acc[4 * k + 1];
        o.z = acc[4 * k + 2];
        o.w = acc[4 * k + 3];
        out4[b * 4 + k] = o;
    }
}

extern "C" void kernel_launch(void* const* d_in, const int* in_sizes, int n_in,
                              void* d_out, int out_size)
{
    // Input order (metadata): t, y, forward_rates, reverse_rates, stoich,
    // effects, from_idx, from_valid, to_idx, to_valid, reversible
    const float* y       = (const float*)d_in[1];
    const float* fr      = (const float*)d_in[2];
    const float* rr      = (const float*)d_in[3];
    const float* stoich  = (const float*)d_in[4];
    const float* effects = (const float*)d_in[5];
    const int*   from_i  = (const int*)d_in[6];
    const unsigned char* from_v = (const unsigned char*)d_in[7];
    const int*   to_i    = (const int*)d_in[8];
    const unsigned char* to_v   = (const unsigned char*)d_in[9];
    const unsigned char* rev    = (const unsigned char*)d_in[10];

    prep_kernel<<<1, 1>>>(stoich, effects, from_i, from_v, to_i, to_v, rev);

    const int B = in_sizes[1] / SS;
    const int grid = (B + NTHREADS - 1) / NTHREADS;
    mech_kernel<<<grid, NTHREADS>>>((const float4*)y, (const float4*)fr,
                                    (const float4*)rr, (float4*)d_out, B);
}

// round 2
// speedup vs baseline: 1.1810x; 1.1810x over previous
#include <cuda_runtime.h>

#define TT 12
#define SS 16
#define NTHREADS 256
#define YSTRIDE 17   // 16 species + sentinel 1.0f; 17 coprime with 32 -> conflict-free

// Robustly decode one element of a boolean array whose on-device dtype may be
// int32, uint8/bool, or float32. Detection reads only the first 12 bytes
// (safe under every hypothesis: 12 elements of any of those dtypes >= 12 B).
__device__ __forceinline__ int decode_bool_elem(const unsigned char* p, int i) {
    // float32 1.0f has byte pattern [00 00 80 3F]
    bool is_f32 = false;
    #pragma unroll
    for (int k = 0; k < 3; k++)
        if (p[4 * k + 2] == 0x80 && p[4 * k + 3] == 0x3F) is_f32 = true;
    if (is_f32) {
        return (((const float*)p)[i] != 0.0f) ? 1 : 0;
    }
    // uint8/bool: nonzero bytes appear at non-multiple-of-4 positions
    bool off_nonzero = false;
    #pragma unroll
    for (int j = 0; j < 12; j++)
        if ((j & 3) && p[j]) off_nonzero = true;
    if (off_nonzero) {
        return (p[i] != 0) ? 1 : 0;
    }
    // int32 (values 0/1, little-endian)
    return (((const int*)p)[i] != 0) ? 1 : 0;
}

__global__ void __launch_bounds__(NTHREADS, 4)
mech_kernel(const float4* __restrict__ y4,
            const float4* __restrict__ f4,
            const float4* __restrict__ r4,
            float4* __restrict__ out4,
            const float* __restrict__ stoich,
            const float* __restrict__ effects,
            const int* __restrict__ from_idx,
            const unsigned char* __restrict__ from_valid,
            const int* __restrict__ to_idx,
            const unsigned char* __restrict__ to_valid,
            const unsigned char* __restrict__ reversible,
            int B)
{
    __shared__ float ys[NTHREADS * YSTRIDE];
    __shared__ float s_eff[TT][SS];
    __shared__ int   s_sub[TT], s_prod[TT], s_fr[TT], s_to[TT];
    __shared__ float s_rev[TT];

    const int tid = threadIdx.x;

    // ---- per-block mechanism prep (tiny, all L2 hits after first wave) ----
    if (tid < TT) {
        const int t = tid;
        int sub = -1, prod = -1;
        #pragma unroll
        for (int s = 0; s < SS; s++) {
            float v = stoich[t * SS + s];
            if (v < -0.5f) sub = s;
            if (v >  0.5f) prod = s;
        }
        s_sub[t]  = (sub  >= 0) ? sub  : 16;
        s_prod[t] = (prod >= 0) ? prod : 16;
        s_fr[t]   = decode_bool_elem(from_valid, t) ? from_idx[t] : 16;
        s_to[t]   = decode_bool_elem(to_valid,  t)  ? to_idx[t]   : 16;
        s_rev[t]  = decode_bool_elem(reversible, t) ? 1.0f : 0.0f;
    }
    for (int i = tid; i < TT * SS; i += NTHREADS)
        (&s_eff[0][0])[i] = effects[i];

    // ---- stage this thread's rows (ys is thread-private scratch) ----
    const long b = (long)blockIdx.x * NTHREADS + tid;
    const bool active = (b < B);
    const int base = tid * YSTRIDE;

    float fv[TT], rv[TT];
    if (active) {
        #pragma unroll
        for (int k = 0; k < 4; k++) {
            float4 v = y4[b * 4 + k];
            ys[base + 4 * k + 0] = v.x;
            ys[base + 4 * k + 1] = v.y;
            ys[base + 4 * k + 2] = v.z;
            ys[base + 4 * k + 3] = v.w;
        }
        ys[base + 16] = 1.0f;  // sentinel for invalid enzyme / missing product

        #pragma unroll
        for (int k = 0; k < 3; k++) {
            float4 a = f4[b * 3 + k];
            fv[4 * k + 0] = a.x; fv[4 * k + 1] = a.y;
            fv[4 * k + 2] = a.z; fv[4 * k + 3] = a.w;
            float4 c = r4[b * 3 + k];
            rv[4 * k + 0] = c.x; rv[4 * k + 1] = c.y;
            rv[4 * k + 2] = c.z; rv[4 * k + 3] = c.w;
        }
    }
    __syncthreads();

    if (!active) return;

    float acc[SS];
    #pragma unroll
    for (int s = 0; s < SS; s++) acc[s] = 0.0f;

    #pragma unroll
    for (int t = 0; t < TT; t++) {
        // Indices are uniform across the warp; stride 17 keeps banks distinct.
        float sc = ys[base + s_sub[t]];
        float ef = ys[base + s_fr[t]];
        float pc = ys[base + s_prod[t]];
        float er = ys[base + s_to[t]];
        float v  = fv[t] * ef * sc - s_rev[t] * rv[t] * er * pc;
        #pragma unroll
        for (int s = 0; s < SS; s++)
            acc[s] = fmaf(v, s_eff[t][s], acc[s]);
    }

    #pragma unroll
    for (int k = 0; k < 4; k++) {
        float4 o;
        o.x = acc[4 * k + 0];
        o.y = acc[4 * k + 1];
        o.z = acc[4 * k + 2];
        o.w = acc[4 * k + 3];
        out4[b * 4 + k] = o;
    }
}

extern "C" void kernel_launch(void* const* d_in, const int* in_sizes, int n_in,
                              void* d_out, int out_size)
{
    // Input order: t, y, forward_rates, reverse_rates, stoich, effects,
    // from_idx, from_valid, to_idx, to_valid, reversible
    const float* y       = (const float*)d_in[1];
    const float* fr      = (const float*)d_in[2];
    const float* rr      = (const float*)d_in[3];
    const float* stoich  = (const float*)d_in[4];
    const float* effects = (const float*)d_in[5];
    const int*   from_i  = (const int*)d_in[6];
    const unsigned char* from_v = (const unsigned char*)d_in[7];
    const int*   to_i    = (const int*)d_in[8];
    const unsigned char* to_v   = (const unsigned char*)d_in[9];
    const unsigned char* rev    = (const unsigned char*)d_in[10];

    const int B = in_sizes[1] / SS;
    const int grid = (B + NTHREADS - 1) / NTHREADS;
    mech_kernel<<<grid, NTHREADS>>>((const float4*)y, (const float4*)fr,
                                    (const float4*)rr, (float4*)d_out,
                                    stoich, effects, from_i, from_v,
                                    to_i, to_v, rev, B);
}

// round 3
// speedup vs baseline: 1.3249x; 1.1218x over previous
#include <cuda_runtime.h>

#define TT 12
#define SS 16
#define NTHREADS 256
#define YS 17   // y row stride: 16 species + sentinel; odd -> conflict-free gathers
#define FS 13   // rate row stride: 12 rates + pad; odd -> conflict-free reads

// Robustly decode one element of a boolean array whose on-device dtype may be
// int32, uint8/bool, or float32. Detection reads only the first 12 bytes.
__device__ __forceinline__ int decode_bool_elem(const unsigned char* p, int i) {
    bool is_f32 = false;                       // float32 1.0f = [00 00 80 3F]
    #pragma unroll
    for (int k = 0; k < 3; k++)
        if (p[4 * k + 2] == 0x80 && p[4 * k + 3] == 0x3F) is_f32 = true;
    if (is_f32) return (((const float*)p)[i] != 0.0f) ? 1 : 0;
    bool off_nonzero = false;                  // uint8: nonzero at off-word bytes
    #pragma unroll
    for (int j = 0; j < 12; j++)
        if ((j & 3) && p[j]) off_nonzero = true;
    if (off_nonzero) return (p[i] != 0) ? 1 : 0;
    return (((const int*)p)[i] != 0) ? 1 : 0;  // int32
}

__global__ void __launch_bounds__(NTHREADS)
mech_kernel(const float4* __restrict__ y4,
            const float4* __restrict__ f4,
            const float4* __restrict__ r4,
            float4* __restrict__ out4,
            const float* __restrict__ stoich,
            const float* __restrict__ effects,
            const int* __restrict__ from_idx,
            const unsigned char* __restrict__ from_valid,
            const int* __restrict__ to_idx,
            const unsigned char* __restrict__ to_valid,
            const unsigned char* __restrict__ reversible,
            int B)
{
    __shared__ float ys[NTHREADS * YS];
    __shared__ float fs[NTHREADS * FS];
    __shared__ float rs[NTHREADS * FS];
    __shared__ float s_eff[TT][SS];
    __shared__ int   s_sub[TT], s_prod[TT], s_fr[TT], s_to[TT];
    __shared__ float s_rev[TT];

    const int tid  = threadIdx.x;
    const int row0 = blockIdx.x * NTHREADS;
    const int nrow = min(NTHREADS, B - row0);

    // ---- coalesced staging: consecutive lanes load consecutive float4s ----
    #pragma unroll
    for (int k = 0; k < 4; k++) {               // y: nrow*4 float4s
        int idx = tid + k * NTHREADS;
        if (idx < nrow * 4) {
            float4 v = y4[(long)row0 * 4 + idx];
            int r = idx >> 2, p = (idx & 3) * 4;
            ys[r * YS + p + 0] = v.x; ys[r * YS + p + 1] = v.y;
            ys[r * YS + p + 2] = v.z; ys[r * YS + p + 3] = v.w;
        }
    }
    ys[tid * YS + 16] = 1.0f;                   // sentinel (own region)

    #pragma unroll
    for (int k = 0; k < 3; k++) {               // f and r: nrow*3 float4s each
        int idx = tid + k * NTHREADS;
        if (idx < nrow * 3) {
            int r = idx / 3, p = (idx - r * 3) * 4;
            float4 a = f4[(long)row0 * 3 + idx];
            fs[r * FS + p + 0] = a.x; fs[r * FS + p + 1] = a.y;
            fs[r * FS + p + 2] = a.z; fs[r * FS + p + 3] = a.w;
            float4 c = r4[(long)row0 * 3 + idx];
            rs[r * FS + p + 0] = c.x; rs[r * FS + p + 1] = c.y;
            rs[r * FS + p + 2] = c.z; rs[r * FS + p + 3] = c.w;
        }
    }

    // ---- per-block mechanism prep (tiny; L2 hits after first wave) ----
    if (tid < TT) {
        const int t = tid;
        int sub = -1, prod = -1;
        #pragma unroll
        for (int s = 0; s < SS; s++) {
            float v = stoich[t * SS + s];
            if (v < -0.5f) sub = s;
            if (v >  0.5f) prod = s;
        }
        s_sub[t]  = (sub  >= 0) ? sub  : 16;
        s_prod[t] = (prod >= 0) ? prod : 16;
        s_fr[t]   = decode_bool_elem(from_valid, t) ? from_idx[t] : 16;
        s_to[t]   = decode_bool_elem(to_valid,  t)  ? to_idx[t]   : 16;
        s_rev[t]  = decode_bool_elem(reversible, t) ? 1.0f : 0.0f;
    }
    for (int i = tid; i < TT * SS; i += NTHREADS)
        (&s_eff[0][0])[i] = effects[i];

    __syncthreads();

    // ---- compute (all smem reads are from this thread's own padded rows) ----
    if (tid < nrow) {
        const int yb = tid * YS;
        const int fb = tid * FS;

        float acc[SS];
        #pragma unroll
        for (int s = 0; s < SS; s++) acc[s] = 0.0f;

        #pragma unroll
        for (int t = 0; t < TT; t++) {
            float sc = ys[yb + s_sub[t]];
            float ef = ys[yb + s_fr[t]];
            float pc = ys[yb + s_prod[t]];
            float er = ys[yb + s_to[t]];
            float v  = fs[fb + t] * ef * sc - s_rev[t] * rs[fb + t] * er * pc;
            #pragma unroll
            for (int s = 0; s < SS; s++)
                acc[s] = fmaf(v, s_eff[t][s], acc[s]);
        }

        // park result in own ys row (gathers done; own region, no barrier yet)
        #pragma unroll
        for (int s = 0; s < SS; s++) ys[yb + s] = acc[s];
    }
    __syncthreads();

    // ---- coalesced store ----
    #pragma unroll
    for (int k = 0; k < 4; k++) {
        int idx = tid + k * NTHREADS;
        if (idx < nrow * 4) {
            int r = idx >> 2, p = (idx & 3) * 4;
            float4 o;
            o.x = ys[r * YS + p + 0]; o.y = ys[r * YS + p + 1];
            o.z = ys[r * YS + p + 2]; o.w = ys[r * YS + p + 3];
            out4[(long)row0 * 4 + idx] = o;
        }
    }
}

extern "C" void kernel_launch(void* const* d_in, const int* in_sizes, int n_in,
                              void* d_out, int out_size)
{
    // Input order: t, y, forward_rates, reverse_rates, stoich, effects,
    // from_idx, from_valid, to_idx, to_valid, reversible
    const float* y       = (const float*)d_in[1];
    const float* fr      = (const float*)d_in[2];
    const float* rr      = (const float*)d_in[3];
    const float* stoich  = (const float*)d_in[4];
    const float* effects = (const float*)d_in[5];
    const int*   from_i  = (const int*)d_in[6];
    const unsigned char* from_v = (const unsigned char*)d_in[7];
    const int*   to_i    = (const int*)d_in[8];
    const unsigned char* to_v   = (const unsigned char*)d_in[9];
    const unsigned char* rev    = (const unsigned char*)d_in[10];

    const int B = in_sizes[1] / SS;
    const int grid = (B + NTHREADS - 1) / NTHREADS;
    mech_kernel<<<grid, NTHREADS>>>((const float4*)y, (const float4*)fr,
                                    (const float4*)rr, (float4*)d_out,
                                    stoich, effects, from_i, from_v,
                                    to_i, to_v, rev, B);
}